// round 15
// baseline (speedup 1.0000x reference)
#include <cuda_runtime.h>
#include <cuda_bf16.h>
#include <cstdint>

// Dequant: out[r][c] = (float)q[r][c] * row_stats[r] * (1/127)
// ROWS = COLS = 8192, int32 in -> fp32 out. Pure streaming: 512 MiB total.
//
// FINAL — measured-best config, reproduced 8x across R3-R14
// (kernel 73.9-75.2us, end-to-end 82.0us). Exhaustive sweep (kernel us):
//   width/MLP: 128b x1 82.5 | x4 74.5 | x8 73.9 | 256b x4 75.2  (saturated)
//   stores:    .cs 73.9 | .wt 75.3 | default 75.5
//   layout:    4KB-strided 73.9 | contiguous-per-warp 75.2 (LTS addr hash
//              defeats software DRAM-locality schemes, per B300_MICROARCH)
//   grid:      oversubscribed 8192 CTAs 73.9 | persistent 912 CTAs 78.9
//              (oversubscription IS the latency hider; persistent loop
//               collapses MLP to 0 at every row seam)
//   blocksize: TPB 256 vs 128 — neutral (issue slack everywhere)
// Config: one block == one row (256 thr x 8 int4 = 8192 cols), uniform
// per-block scale (single __ldg), 8 front-batched LDG.E.128 (MLP=8),
// .cs streaming hints on both loads and stores.
// All variants sit at 80-82% DRAM-active (~6.4-6.5 TB/s): the B300 mixed
// 1:1 read/write HBM-stream ceiling. Traffic is fixed by the I/O contract
// (int32 in, fp32 out) — no format freedom. Roofline reached.

#define VPT 8                         // int4 vectors per thread
#define TPB 256                       // TPB*VPT = 2048 vecs = 8192 cols = 1 row

__global__ void __launch_bounds__(TPB, 6)
dequant_kernel(const int4* __restrict__ q,
               const float* __restrict__ row_stats,
               float4* __restrict__ out)
{
    // Uniform per-block scale: block r handles row r.
    const float scale = __ldg(&row_stats[blockIdx.x]) * (1.0f / 127.0f);

    const int base = blockIdx.x * (TPB * VPT) + threadIdx.x;

    // Front-batch 8 independent LDG.E.128 (MLP=8), streaming hint.
    int4 v[VPT];
#pragma unroll
    for (int j = 0; j < VPT; j++)
        v[j] = __ldcs(&q[base + j * TPB]);

#pragma unroll
    for (int j = 0; j < VPT; j++) {
        float4 r;
        r.x = (float)v[j].x * scale;
        r.y = (float)v[j].y * scale;
        r.z = (float)v[j].z * scale;
        r.w = (float)v[j].w * scale;
        __stcs(&out[base + j * TPB], r);   // streaming store (measured best)
    }
}

extern "C" void kernel_launch(void* const* d_in, const int* in_sizes, int n_in,
                              void* d_out, int out_size)
{
    const int4*  q         = (const int4*)d_in[0];   // int32 [8192,8192]
    const float* row_stats = (const float*)d_in[1];  // fp32  [8192]
    float4*      out       = (float4*)d_out;

    const int rows = in_sizes[1];                    // 8192 blocks, one per row

    dequant_kernel<<<rows, TPB>>>(q, row_stats, out);
}

// round 16
// speedup vs baseline: 1.0023x; 1.0023x over previous
#include <cuda_runtime.h>
#include <cuda_bf16.h>
#include <cstdint>

// Dequant: out[r][c] = (float)q[r][c] * row_stats[r] * (1/127)
// ROWS = COLS = 8192, int32 in -> fp32 out. Pure streaming: 512 MiB total.
//
// R16: measured-best R3 schedule + L2::256B prefetch hint on the load
// stream (ld.global.cs.L2::256B.v4.b32 — not emittable from C++). Each LDG
// fills a 256B L2 granule instead of a demand 128B line, halving the count
// of independent L2->DRAM read requests contending with the write stream
// (read/write turnaround = the identified residual vs 100% DRAM-active).
// Adjacent warps consume the prefetched halves -> zero waste traffic.
// Everything else identical to the 9x-reproduced best config: one block ==
// one row, uniform per-block scale, 8 front-batched 128b loads (MLP=8),
// .cs streaming on loads and stores.

#define VPT 8                         // int4 vectors per thread
#define TPB 256                       // TPB*VPT = 2048 vecs = 8192 cols = 1 row

__device__ __forceinline__ int4 ldg128_cs_l2_256(const int4* p) {
    int4 v;
    asm volatile("ld.global.cs.L2::256B.v4.b32 {%0,%1,%2,%3}, [%4];"
                 : "=r"(v.x), "=r"(v.y), "=r"(v.z), "=r"(v.w)
                 : "l"(p));
    return v;
}

__global__ void __launch_bounds__(TPB, 6)
dequant_kernel(const int4* __restrict__ q,
               const float* __restrict__ row_stats,
               float4* __restrict__ out)
{
    // Uniform per-block scale: block r handles row r.
    const float scale = __ldg(&row_stats[blockIdx.x]) * (1.0f / 127.0f);

    const int base = blockIdx.x * (TPB * VPT) + threadIdx.x;

    // Front-batch 8 independent LDG.E.128 (MLP=8), streaming + L2::256B.
    int4 v[VPT];
#pragma unroll
    for (int j = 0; j < VPT; j++)
        v[j] = ldg128_cs_l2_256(&q[base + j * TPB]);

#pragma unroll
    for (int j = 0; j < VPT; j++) {
        float4 r;
        r.x = (float)v[j].x * scale;
        r.y = (float)v[j].y * scale;
        r.z = (float)v[j].z * scale;
        r.w = (float)v[j].w * scale;
        __stcs(&out[base + j * TPB], r);   // streaming store (measured best)
    }
}

extern "C" void kernel_launch(void* const* d_in, const int* in_sizes, int n_in,
                              void* d_out, int out_size)
{
    const int4*  q         = (const int4*)d_in[0];   // int32 [8192,8192]
    const float* row_stats = (const float*)d_in[1];  // fp32  [8192]
    float4*      out       = (float4*)d_out;

    const int rows = in_sizes[1];                    // 8192 blocks, one per row

    dequant_kernel<<<rows, TPB>>>(q, row_stats, out);
}